// round 8
// baseline (speedup 1.0000x reference)
#include <cuda_runtime.h>
#include <stdint.h>

typedef unsigned long long u64;

#define IN_CH     128
#define OC        64
#define MAX_NODES 100000
#define BM        128
#define KC        32
#define NCHUNK    (IN_CH / KC)     // 4
#define XSTR2     130              // u64 stride per k-row of xsd (128 + 2 pad)
#define XSD_U64   (KC * XSTR2)     // u64s per x buffer (4160)
#define WS_OFF    (2 * XSD_U64)    // ws starts after the two x buffers
#define DSMEM_BYTES ((WS_OFF + IN_CH * 32) * 8)   // 99,328 B

__device__ unsigned int g_mask[MAX_NODES];

// ---- zero mask (vectorized) ------------------------------------------------
__global__ void k_zero_mask(int n4, int n) {
    int i = blockIdx.x * blockDim.x + threadIdx.x;
    if (i < n4) reinterpret_cast<uint4*>(g_mask)[i] = make_uint4(0u, 0u, 0u, 0u);
    int t = n4 * 4 + i;
    if (t < n) g_mask[t] = 0u;   // scalar tail
}

// ---- scatter with fused dtype detection ------------------------------------
// int64 view of int64 data: node ids < 1e5 -> every odd 32-bit word is 0.
__global__ void k_scatter_mask(const unsigned int* __restrict__ ei32,
                               const long long* __restrict__ col64,
                               const int* __restrict__ col32,
                               int ne, int n) {
    __shared__ int s_is64;
    if (threadIdx.x < 32) {
        unsigned int w = 0;
        #pragma unroll
        for (int j = threadIdx.x; j < 128; j += 32) w |= ei32[2 * j + 1];
        unsigned int any = __ballot_sync(0xffffffffu, w != 0u);
        if (threadIdx.x == 0) s_is64 = (any == 0u) ? 1 : 0;
    }
    __syncthreads();
    const int is64 = s_is64;

    int i = (blockIdx.x * blockDim.x + threadIdx.x) * 2;
    if (i >= ne) return;
    long long v0, v1;
    if (is64) {
        longlong2 p = *reinterpret_cast<const longlong2*>(col64 + i);
        v0 = p.x; v1 = p.y;
    } else {
        int2 p = *reinterpret_cast<const int2*>(col32 + i);
        v0 = p.x; v1 = p.y;
    }
    if (v0 >= 0 && v0 < n) g_mask[(int)v0] = 1u;
    if (i + 1 < ne && v1 >= 0 && v1 < n) g_mask[(int)v1] = 1u;
}

// ---- packed math -----------------------------------------------------------
__device__ __forceinline__ u64 ffma2(u64 a, u64 b, u64 c) {
    u64 d;
    asm("fma.rn.f32x2 %0, %1, %2, %3;" : "=l"(d) : "l"(a), "l"(b), "l"(c));
    return d;
}
__device__ __forceinline__ u64 dup2(float a) {
    u64 d;
    asm("mov.b64 %0, {%1, %1};" : "=l"(d) : "f"(a));
    return d;
}

// ---- GEMM: out[r,:] = mask[r] ? x[r,:] @ W : 0 -----------------------------
// 256 threads; tile BM=128 x OC=64. Warp w: col group cgi = w&3 (uniform per
// warp -> W LDS are single-address broadcasts); row pair rp = (w>>2)*32+lane.
// smem: xsd[2][KC][XSTR2] u64 (x transposed AND pre-duplicated: (v,v)),
//       ws[128][32]       u64 (W verbatim: (W[k][2j], W[k][2j+1])).
// Per k: 1 LDS.128 (both dup'd rows) + 4 LDS.128 (W bcast) + 16 FFMA2 = 21 issues.
// x chunks double-buffered; next chunk's LDGs issued before the k-loop.
__global__ __launch_bounds__(256, 2) void k_gemm_mask(
    const float* __restrict__ x,
    const float* __restrict__ W,
    float* __restrict__ out,
    int n)
{
    extern __shared__ __align__(16) u64 smem[];
    u64* xsd = smem;            // 2 buffers
    u64* ws  = smem + WS_OFF;   // whole W

    const int tid  = threadIdx.x;
    const int w    = tid >> 5;
    const int lane = tid & 31;
    const int cgi  = w & 3;                   // column group (warp-uniform)
    const int rp   = ((w >> 2) << 5) + lane;  // row pair 0..63
    const int row0 = blockIdx.x * BM;

    // thread's staging coords: f = tid + jj*256 -> r = f>>3, c4 = f&7
    const int st_r  = tid >> 3;         // base row for jj=0 (0..31)
    const int st_c4 = tid & 7;

    // ---- stage all of W (32KB, verbatim float4 copy)
    {
        const float4* src = reinterpret_cast<const float4*>(W);
        float4*       dst = reinterpret_cast<float4*>(ws);
        #pragma unroll
        for (int j = 0; j < 8; j++) dst[tid + j * 256] = src[tid + j * 256];
    }

    // ---- stage x chunk 0 (transposed + duplicated)
    {
        #pragma unroll
        for (int jj = 0; jj < 4; jj++) {
            int r    = st_r + jj * 32;
            int grow = row0 + r;
            float4 v = make_float4(0.f, 0.f, 0.f, 0.f);
            if (grow < n)
                v = *reinterpret_cast<const float4*>(x + (size_t)grow * IN_CH + st_c4 * 4);
            u64* dstp = xsd + r;
            dstp[(st_c4 * 4 + 0) * XSTR2] = dup2(v.x);
            dstp[(st_c4 * 4 + 1) * XSTR2] = dup2(v.y);
            dstp[(st_c4 * 4 + 2) * XSTR2] = dup2(v.z);
            dstp[(st_c4 * 4 + 3) * XSTR2] = dup2(v.w);
        }
    }
    __syncthreads();

    u64 acc0[8], acc1[8];
    #pragma unroll
    for (int j = 0; j < 8; j++) { acc0[j] = 0ull; acc1[j] = 0ull; }

    int buf = 0;
    #pragma unroll 1
    for (int kc = 0; kc < NCHUNK; kc++) {
        // ---- prefetch next chunk's x into registers (hidden under k-loop)
        float4 pf[4];
        if (kc + 1 < NCHUNK) {
            #pragma unroll
            for (int jj = 0; jj < 4; jj++) {
                int grow = row0 + st_r + jj * 32;
                pf[jj] = make_float4(0.f, 0.f, 0.f, 0.f);
                if (grow < n)
                    pf[jj] = *reinterpret_cast<const float4*>(
                        x + (size_t)grow * IN_CH + (kc + 1) * KC + st_c4 * 4);
            }
        }

        // ---- mainloop over this chunk
        const u64* xb = xsd + buf * XSD_U64;
        const u64* wb = ws + (kc * KC) * 32 + cgi * 8;
        #pragma unroll 8
        for (int k = 0; k < KC; k++) {
            ulonglong2 xv = *reinterpret_cast<const ulonglong2*>(xb + k * XSTR2 + 2 * rp);
            const ulonglong2* wp = reinterpret_cast<const ulonglong2*>(wb + k * 32);
            #pragma unroll
            for (int q = 0; q < 4; q++) {
                ulonglong2 wv = wp[q];
                acc0[2*q]   = ffma2(xv.x, wv.x, acc0[2*q]);
                acc0[2*q+1] = ffma2(xv.x, wv.y, acc0[2*q+1]);
                acc1[2*q]   = ffma2(xv.y, wv.x, acc1[2*q]);
                acc1[2*q+1] = ffma2(xv.y, wv.y, acc1[2*q+1]);
            }
        }

        // ---- store prefetched chunk into the other buffer, swap
        if (kc + 1 < NCHUNK) {
            u64* dstb = xsd + (buf ^ 1) * XSD_U64;
            #pragma unroll
            for (int jj = 0; jj < 4; jj++) {
                int r = st_r + jj * 32;
                u64* dstp = dstb + r;
                dstp[(st_c4 * 4 + 0) * XSTR2] = dup2(pf[jj].x);
                dstp[(st_c4 * 4 + 1) * XSTR2] = dup2(pf[jj].y);
                dstp[(st_c4 * 4 + 2) * XSTR2] = dup2(pf[jj].z);
                dstp[(st_c4 * 4 + 3) * XSTR2] = dup2(pf[jj].w);
            }
            __syncthreads();
            buf ^= 1;
        }
    }

    // ---- epilogue: 2 rows, mask + 4 float4 stores per row
    const int r0 = row0 + 2 * rp;
    const int r1 = r0 + 1;
    const float m0 = (r0 < n && g_mask[r0]) ? 1.0f : 0.0f;
    const float m1 = (r1 < n && g_mask[r1]) ? 1.0f : 0.0f;

    #pragma unroll
    for (int q = 0; q < 4; q++) {
        if (r0 < n) {
            u64 pa = acc0[2*q], pb = acc0[2*q+1];
            *reinterpret_cast<float4*>(out + (size_t)r0 * OC + cgi * 16 + 4 * q) =
                make_float4(__uint_as_float((unsigned int)pa) * m0,
                            __uint_as_float((unsigned int)(pa >> 32)) * m0,
                            __uint_as_float((unsigned int)pb) * m0,
                            __uint_as_float((unsigned int)(pb >> 32)) * m0);
        }
        if (r1 < n) {
            u64 pa = acc1[2*q], pb = acc1[2*q+1];
            *reinterpret_cast<float4*>(out + (size_t)r1 * OC + cgi * 16 + 4 * q) =
                make_float4(__uint_as_float((unsigned int)pa) * m1,
                            __uint_as_float((unsigned int)(pa >> 32)) * m1,
                            __uint_as_float((unsigned int)pb) * m1,
                            __uint_as_float((unsigned int)(pb >> 32)) * m1);
        }
    }
}

extern "C" void kernel_launch(void* const* d_in, const int* in_sizes, int n_in,
                              void* d_out, int out_size)
{
    // metadata order: x, edge_index, edge_attr, W, W_edge, a
    const float* x   = (const float*)d_in[0];
    const void*  ei  = d_in[1];                 // int64 or int32 [2, E], detected on device
    const float* W   = (const float*)d_in[3];   // [128, 64] row-major
    float*       out = (float*)d_out;

    const int n  = in_sizes[0] / IN_CH;   // 100000
    const int ne = in_sizes[1] / 2;       // 1600000

    const long long* col64 = (const long long*)ei + ne;
    const int*       col32 = (const int*)ei + ne;

    static int smem_set = 0;
    if (!smem_set) {
        cudaFuncSetAttribute(k_gemm_mask,
                             cudaFuncAttributeMaxDynamicSharedMemorySize, DSMEM_BYTES);
        smem_set = 1;
    }

    int n4 = n / 4;
    k_zero_mask   <<<(n4 + 255) / 256, 256>>>(n4, n);
    k_scatter_mask<<<(ne / 2 + 255) / 256, 256>>>((const unsigned int*)ei, col64, col32, ne, n);
    k_gemm_mask   <<<(n + BM - 1) / BM, 256, DSMEM_BYTES>>>(x, W, out, n);
}